// round 10
// baseline (speedup 1.0000x reference)
#include <cuda_runtime.h>
#include <cuda_fp16.h>
#include <cstdint>

// Problem constants
#define BB 16
#define SS 2048
#define HH 512
#define AA 256
#define BS (BB*SS)               // 32768 tokens
#define A_ELEMS ((size_t)BS*HH)  // offset of d in output

// Scratch (device globals — no allocation allowed)
__device__ float g_e[BS];
__device__ float g_w[BS];
__device__ float g_ip[BS];
#define NC 64
#define CS 32
__device__ float g_agg[BB*NC*HH];   // per-chunk aggregates (2 MB)
__device__ int   g_flag[BB*NC];     // decoupled-lookback flags
// W as fp16 pairs (uint32 = half2), [256 rows][256 pairs]
__device__ unsigned int g_wh[AA*HH/2];

// ---------------------------------------------------------------------------
__device__ __forceinline__ uint32_t smem_u32(const void* p) {
    uint32_t a;
    asm("{ .reg .u64 t; cvta.to.shared.u64 t, %1; cvt.u32.u64 %0, t; }"
        : "=r"(a) : "l"(p));
    return a;
}

#define LDSM_X4(r, addr) \
    asm volatile("ldmatrix.sync.aligned.m8n8.x4.shared.b16 {%0,%1,%2,%3}, [%4];" \
        : "=r"((r)[0]), "=r"((r)[1]), "=r"((r)[2]), "=r"((r)[3]) : "r"(addr))

#define HMMA16816(d, a, b0, b1) \
    asm volatile("mma.sync.aligned.m16n8k16.row.col.f32.f16.f16.f32 " \
        "{%0,%1,%2,%3},{%4,%5,%6,%7},{%8,%9},{%0,%1,%2,%3};" \
        : "+f"((d)[0]), "+f"((d)[1]), "+f"((d)[2]), "+f"((d)[3]) \
        : "r"((a)[0]), "r"((a)[1]), "r"((a)[2]), "r"((a)[3]), "r"(b0), "r"(b1))

#define CP_ASYNC16(dst, src) \
    asm volatile("cp.async.cg.shared.global [%0], [%1], 16;" \
                 :: "r"(dst), "l"(src) : "memory")
#define CP_COMMIT()  asm volatile("cp.async.commit_group;" ::: "memory")
#define CP_WAIT0()   asm volatile("cp.async.wait_group 0;" ::: "memory")

__device__ __forceinline__ float fast_tanh(float v) {
    float t; asm("ex2.approx.f32 %0, %1;" : "=f"(t) : "f"(v * 2.885390081777927f));
    float r; asm("rcp.approx.f32 %0, %1;" : "=f"(r) : "f"(t + 1.0f));
    return fmaf(-2.0f, r, 1.0f);   // tanh(v) = 1 - 2/(e^{2v}+1)
}

// ---------------------------------------------------------------------------
// Kernel 0: W [256,512] fp32 -> fp16 pairs
// ---------------------------------------------------------------------------
__global__ __launch_bounds__(256) void wsplit_kernel(const float* __restrict__ W)
{
    const int i = blockIdx.x * 256 + threadIdx.x;   // pair index
    const float2 v = ((const float2*)W)[i];
    __half2 hp = __floats2half2_rn(v.x, v.y);
    g_wh[i] = *(unsigned int*)&hp;
}

// ---------------------------------------------------------------------------
// Kernel 1: e[t] = sum_a q[a]*tanh( (W x)[t,a] ) via mma.sync fp16.
// CTA tile: M=64 tokens x N=256 (FULL A). 8 warps as 2(m) x 4(n).
// Double-buffered; W via cp.async, X via regs (fp32->fp16 convert).
// ---------------------------------------------------------------------------
#define RSTRIDE 144              // bytes per smem row (64 fp16 + pad)
#define BUFSZ   46080            // X(64*144=9216) + W(256*144=36864)
#define SM_W_OFF 9216
#define SM_Q    92160            // 256 floats
#define SM_TOTAL 93184

__global__ __launch_bounds__(256, 2) void e_mma_kernel(
    const float* __restrict__ x, const float* __restrict__ q)
{
    extern __shared__ __align__(128) char smem[];
    const uint32_t sb = smem_u32(smem);
    const int tid  = threadIdx.x;
    const int lane = tid & 31;
    const int warp = tid >> 5;
    const int warp_m = warp & 1;
    const int warp_n = warp >> 1;
    const size_t m0 = (size_t)blockIdx.x * 64;

    float* sq = (float*)(smem + SM_Q);
    sq[tid] = q[tid];

    float acc[2][8][4];
#pragma unroll
    for (int mt = 0; mt < 2; mt++)
#pragma unroll
        for (int nt = 0; nt < 8; nt++)
#pragma unroll
            for (int j = 0; j < 4; j++) acc[mt][nt][j] = 0.f;

    const uint32_t a_off = (lane & 15) * RSTRIDE + ((lane >> 4) << 4);
    const uint32_t b_off = ((((lane >> 4) & 1) << 3) + (lane & 7)) * RSTRIDE
                         + (((lane >> 3) & 1) << 4);
    const uint32_t ax0 = sb + warp_m * 32 * RSTRIDE + a_off;
    const uint32_t bw0 = sb + SM_W_OFF + warp_n * 64 * RSTRIDE + b_off;

    const uint4* wh4 = (const uint4*)g_wh;   // [a][64 uint4 per row]

    // Prologue: fill buffer 0 for chunk 0
    {
        float4 xv[4];
#pragma unroll
        for (int i = 0; i < 4; i++) {
            const int idx = i * 256 + tid;
            xv[i] = *(const float4*)(x + (m0 + (idx >> 4)) * HH + (idx & 15) * 4);
        }
#pragma unroll
        for (int i = 0; i < 8; i++) {
            const int g  = i * 256 + tid;
            const int row = g >> 3;
            const int cc  = g & 7;
            CP_ASYNC16(sb + SM_W_OFF + row * RSTRIDE + cc * 16,
                       wh4 + (size_t)row * 64 + cc);
        }
        CP_COMMIT();
#pragma unroll
        for (int i = 0; i < 4; i++) {
            const int idx = i * 256 + tid;
            const uint32_t bo = (idx >> 4) * RSTRIDE + (idx & 15) * 8;
            __half2 h01 = __floats2half2_rn(xv[i].x, xv[i].y);
            __half2 h23 = __floats2half2_rn(xv[i].z, xv[i].w);
            unsigned long long hp;
            asm("mov.b64 %0, {%1, %2};" : "=l"(hp)
                : "r"(*(unsigned int*)&h01), "r"(*(unsigned int*)&h23));
            *(unsigned long long*)(smem + bo) = hp;
        }
        CP_WAIT0();
        __syncthreads();
    }

    for (int c = 0; c < 8; c++) {
        const uint32_t cur = (c & 1) * BUFSZ;
        const uint32_t nxt = ((c + 1) & 1) * BUFSZ;

        float4 xv[4];
        if (c < 7) {
            const int kk = (c + 1) * 64;
#pragma unroll
            for (int i = 0; i < 4; i++) {
                const int idx = i * 256 + tid;
                xv[i] = *(const float4*)(x + (m0 + (idx >> 4)) * HH + kk + (idx & 15) * 4);
            }
#pragma unroll
            for (int i = 0; i < 8; i++) {
                const int g  = i * 256 + tid;
                const int row = g >> 3;
                const int cc  = g & 7;
                CP_ASYNC16(sb + nxt + SM_W_OFF + row * RSTRIDE + cc * 16,
                           wh4 + (size_t)row * 64 + (kk >> 3) + cc);
            }
            CP_COMMIT();
        }

        const uint32_t ax = ax0 + cur;
        const uint32_t bw = bw0 + cur;
#pragma unroll
        for (int ks = 0; ks < 4; ks++) {
            uint32_t Bv[16];
#pragma unroll
            for (int jp = 0; jp < 4; jp++)
                LDSM_X4(&Bv[jp * 4], bw + jp * 16 * RSTRIDE + ks * 32);
            uint32_t A0[4], A1[4];
            LDSM_X4(A0, ax + ks * 32);
            LDSM_X4(A1, ax + 16 * RSTRIDE + ks * 32);
#pragma unroll
            for (int nt = 0; nt < 8; nt++) {
                const int bi = (nt >> 1) * 4 + (nt & 1) * 2;
                HMMA16816(acc[0][nt], A0, Bv[bi], Bv[bi + 1]);
            }
#pragma unroll
            for (int nt = 0; nt < 8; nt++) {
                const int bi = (nt >> 1) * 4 + (nt & 1) * 2;
                HMMA16816(acc[1][nt], A1, Bv[bi], Bv[bi + 1]);
            }
        }

        if (c < 7) {
#pragma unroll
            for (int i = 0; i < 4; i++) {
                const int idx = i * 256 + tid;
                const uint32_t bo = (idx >> 4) * RSTRIDE + (idx & 15) * 8;
                __half2 h01 = __floats2half2_rn(xv[i].x, xv[i].y);
                __half2 h23 = __floats2half2_rn(xv[i].z, xv[i].w);
                unsigned long long hp;
                asm("mov.b64 %0, {%1, %2};" : "=l"(hp)
                    : "r"(*(unsigned int*)&h01), "r"(*(unsigned int*)&h23));
                *(unsigned long long*)(smem + nxt + bo) = hp;
            }
            CP_WAIT0();
            __syncthreads();
        }
    }

    // Epilogue: s = sum_cols q[col]*tanh(D) per owned row
    float s[2][2] = {{0.f, 0.f}, {0.f, 0.f}};
#pragma unroll
    for (int mt = 0; mt < 2; mt++)
#pragma unroll
        for (int nt = 0; nt < 8; nt++) {
            const int col = warp_n * 64 + nt * 8 + 2 * (lane & 3);
            const float q0 = sq[col], q1 = sq[col + 1];
            s[mt][0] = fmaf(q0, fast_tanh(acc[mt][nt][0]),
                       fmaf(q1, fast_tanh(acc[mt][nt][1]), s[mt][0]));
            s[mt][1] = fmaf(q0, fast_tanh(acc[mt][nt][2]),
                       fmaf(q1, fast_tanh(acc[mt][nt][3]), s[mt][1]));
        }
#pragma unroll
    for (int mt = 0; mt < 2; mt++)
#pragma unroll
        for (int rh = 0; rh < 2; rh++) {
            float v = s[mt][rh];
            v += __shfl_xor_sync(0xffffffffu, v, 1);
            v += __shfl_xor_sync(0xffffffffu, v, 2);
            s[mt][rh] = v;
        }

    __syncthreads();               // all ldmatrix done; reuse smem
    float* red = (float*)smem;     // [4 warp_n][64 rows]
    if ((lane & 3) == 0) {
#pragma unroll
        for (int mt = 0; mt < 2; mt++)
#pragma unroll
            for (int rh = 0; rh < 2; rh++)
                red[warp_n * 64 + warp_m * 32 + mt * 16 + rh * 8 + (lane >> 2)]
                    = s[mt][rh];
    }
    __syncthreads();
    if (tid < 64)
        g_e[m0 + tid] = (red[tid] + red[64 + tid])
                      + (red[128 + tid] + red[192 + tid]);
}

// ---------------------------------------------------------------------------
// Kernel 2: per-batch  w_t = exp(e_t - max), inclusive prefix P_s, ip = 1/P_s.
// Also zeroes the lookback flags for this replay.
// ---------------------------------------------------------------------------
__global__ __launch_bounds__(256) void scan_kernel()
{
    __shared__ float se[SS];
    __shared__ float sr[256];
    const int b   = blockIdx.x;
    const int tid = threadIdx.x;
    const int base = b * SS;

    if (tid < NC) g_flag[b * NC + tid] = 0;   // reset lookback flags

    for (int i = tid; i < SS; i += 256) se[i] = g_e[base + i];
    __syncthreads();

    float m = -1e30f;
    for (int i = tid; i < SS; i += 256) m = fmaxf(m, se[i]);
    sr[tid] = m;
    __syncthreads();
    for (int o = 128; o; o >>= 1) {
        if (tid < o) sr[tid] = fmaxf(sr[tid], sr[tid + o]);
        __syncthreads();
    }
    const float M = sr[0];
    __syncthreads();

    const int j0 = tid * 8;
    float wloc[8];
    float run = 0.f;
#pragma unroll
    for (int j = 0; j < 8; j++) {
        wloc[j] = expf(se[j0 + j] - M);
        run += wloc[j];
    }
    sr[tid] = run;
    __syncthreads();
    for (int o = 1; o < 256; o <<= 1) {
        const float v = (tid >= o) ? sr[tid - o] : 0.f;
        __syncthreads();
        sr[tid] += v;
        __syncthreads();
    }
    float acc = sr[tid] - run;
#pragma unroll
    for (int j = 0; j < 8; j++) {
        acc += wloc[j];
        g_w [base + j0 + j] = wloc[j];
        g_ip[base + j0 + j] = 1.0f / acc;
    }
}

// ---------------------------------------------------------------------------
// Kernel 3 (fused): single-pass chunked prefix for a[b,s,h].
// CTA = one chunk of CS=32 tokens, full H. x tile held in smem (64 KB).
// Decoupled lookback over aggregates only (published before any wait).
// ---------------------------------------------------------------------------
#define ASCAN_SMEM (CS*HH*4)     // 65536
__global__ __launch_bounds__(128) void ascan_kernel(
    const float* __restrict__ x, float* __restrict__ a_out)
{
    extern __shared__ __align__(16) float4 sx4[];   // [CS][128]
    __shared__ float sw[CS];
    __shared__ float sip[CS];
    const int bid = blockIdx.x;          // b*NC + c
    const int b   = bid >> 6;
    const int c   = bid & (NC - 1);
    const int tid = threadIdx.x;
    const int tbase = b * SS + c * CS;

    if (tid < CS) {
        sw [tid] = g_w [tbase + tid];
        sip[tid] = g_ip[tbase + tid];
    }
    __syncthreads();

    // Load x tile into smem + compute chunk aggregate
    const float4* xp = (const float4*)(x + (size_t)tbase * HH) + tid;
    float4 agg = make_float4(0.f, 0.f, 0.f, 0.f);
#pragma unroll
    for (int t = 0; t < CS; t++) {
        const float4 v = xp[t * (HH/4)];
        sx4[t * 128 + tid] = v;
        const float w = sw[t];
        agg.x = fmaf(w, v.x, agg.x);
        agg.y = fmaf(w, v.y, agg.y);
        agg.z = fmaf(w, v.z, agg.z);
        agg.w = fmaf(w, v.w, agg.w);
    }

    // Publish aggregate (unconditional — before any waiting)
    ((float4*)(g_agg + (size_t)bid * HH))[tid] = agg;
    __threadfence();
    __syncthreads();
    if (tid == 0) *((volatile int*)&g_flag[bid]) = 1;

    // Lookback: sum aggregates of chunks [0, c), window of 16
    float4 run = make_float4(0.f, 0.f, 0.f, 0.f);
    int hi = c;
    while (hi > 0) {
        int lo = hi - 16; if (lo < 0) lo = 0;
        const int cnt = hi - lo;
        if (tid < cnt) {
            while (*((volatile int*)&g_flag[(b << 6) + lo + tid]) == 0) {}
        }
        __syncthreads();
        __threadfence();
        for (int i = 0; i < cnt; i++) {
            const float4 v = __ldcg(
                (const float4*)(g_agg + (size_t)((b << 6) + lo + i) * HH) + tid);
            run.x += v.x; run.y += v.y; run.z += v.z; run.w += v.w;
        }
        hi = lo;
    }

    // Outputs from smem-resident x
    float4 acc = run;
    float4* op = (float4*)(a_out + (size_t)tbase * HH) + tid;
#pragma unroll
    for (int t = 0; t < CS; t++) {
        const float4 v = sx4[t * 128 + tid];
        const float w = sw[t];
        acc.x = fmaf(w, v.x, acc.x);
        acc.y = fmaf(w, v.y, acc.y);
        acc.z = fmaf(w, v.z, acc.z);
        acc.w = fmaf(w, v.w, acc.w);
        const float ip = sip[t];
        __stcs(op + t * (HH/4),
               make_float4(acc.x * ip, acc.y * ip, acc.z * ip, acc.w * ip));
    }
}

// ---------------------------------------------------------------------------
// Kernel 4: d[b,s,t] = (t<=s) ? w[b,t]*ip[b,s] : 0  — 16 rows per CTA,
// w row staged in smem once.
// ---------------------------------------------------------------------------
#define DROWS 16
__global__ __launch_bounds__(256) void d_kernel(float* __restrict__ dd)
{
    __shared__ float4 sw4[SS/4];   // 8 KB
    __shared__ float sip[DROWS];
    const int blk = blockIdx.x;            // 2048 blocks
    const int b  = blk >> 7;               // 128 blocks per batch
    const int s0 = (blk & 127) * DROWS;

    const float4* w4 = (const float4*)(g_w + ((size_t)b << 11));
    for (int i = threadIdx.x; i < SS/4; i += 256) sw4[i] = w4[i];
    if (threadIdx.x < DROWS) sip[threadIdx.x] = g_ip[(b << 11) + s0 + threadIdx.x];
    __syncthreads();

#pragma unroll 4
    for (int r = 0; r < DROWS; r++) {
        const int s = s0 + r;
        const float ip = sip[r];
        float4* o4 = (float4*)(dd + ((size_t)(b << 11) + s) * SS);
#pragma unroll
        for (int it = 0; it < 2; it++) {
            const int i = it * 256 + threadIdx.x;
            const int t0 = i * 4;
            float4 out;
            if (t0 + 3 <= s) {
                const float4 wv = sw4[i];
                out.x = wv.x * ip; out.y = wv.y * ip;
                out.z = wv.z * ip; out.w = wv.w * ip;
            } else if (t0 > s) {
                out.x = out.y = out.z = out.w = 0.f;
            } else {
                const float4 wv = sw4[i];
                out.x = (t0     <= s) ? wv.x * ip : 0.f;
                out.y = (t0 + 1 <= s) ? wv.y * ip : 0.f;
                out.z = (t0 + 2 <= s) ? wv.z * ip : 0.f;
                out.w = (t0 + 3 <= s) ? wv.w * ip : 0.f;
            }
            __stcs(o4 + i, out);
        }
    }
}

// ---------------------------------------------------------------------------
extern "C" void kernel_launch(void* const* d_in, const int* in_sizes, int n_in,
                              void* d_out, int out_size)
{
    const float* x = (const float*)d_in[0];   // [B,S,H]
    const float* W = (const float*)d_in[1];   // [A,H]
    const float* q = (const float*)d_in[2];   // [1,A]
    float* a_out = (float*)d_out;             // [B,S,1,H]
    float* dd    = (float*)d_out + A_ELEMS;   // [B,S,1,S]

    cudaFuncSetAttribute(e_mma_kernel,
                         cudaFuncAttributeMaxDynamicSharedMemorySize, SM_TOTAL);
    cudaFuncSetAttribute(ascan_kernel,
                         cudaFuncAttributeMaxDynamicSharedMemorySize, ASCAN_SMEM);

    wsplit_kernel<<<AA * HH / 512, 256>>>(W);
    e_mma_kernel <<<BS / 64, 256, SM_TOTAL>>>(x, q);
    scan_kernel  <<<BB, 256>>>();
    ascan_kernel <<<BB * NC, 128, ASCAN_SMEM>>>(x, a_out);
    d_kernel     <<<BS / DROWS, 256>>>(dd);
}

// round 11
// speedup vs baseline: 1.0661x; 1.0661x over previous
#include <cuda_runtime.h>
#include <cuda_fp16.h>
#include <cstdint>

// Problem constants
#define BB 16
#define SS 2048
#define HH 512
#define AA 256
#define BS (BB*SS)               // 32768 tokens
#define A_ELEMS ((size_t)BS*HH)  // offset of d in output

// Scratch (device globals — no allocation allowed)
__device__ float g_e[BS];
__device__ float g_w[BS];
__device__ float g_ip[BS];
#define NC 128
#define CS 16
__device__ float g_chunk[BB*NC*HH];     // 4 MB
__device__ float g_chunkpre[BB*NC*HH];  // 4 MB (exclusive prefix)
// W as fp16 pairs (uint32 = half2), [256 rows][256 pairs]
__device__ unsigned int g_wh[AA*HH/2];

// ---------------------------------------------------------------------------
__device__ __forceinline__ uint32_t smem_u32(const void* p) {
    uint32_t a;
    asm("{ .reg .u64 t; cvta.to.shared.u64 t, %1; cvt.u32.u64 %0, t; }"
        : "=r"(a) : "l"(p));
    return a;
}

#define LDSM_X4(r, addr) \
    asm volatile("ldmatrix.sync.aligned.m8n8.x4.shared.b16 {%0,%1,%2,%3}, [%4];" \
        : "=r"((r)[0]), "=r"((r)[1]), "=r"((r)[2]), "=r"((r)[3]) : "r"(addr))

#define HMMA16816(d, a, b0, b1) \
    asm volatile("mma.sync.aligned.m16n8k16.row.col.f32.f16.f16.f32 " \
        "{%0,%1,%2,%3},{%4,%5,%6,%7},{%8,%9},{%0,%1,%2,%3};" \
        : "+f"((d)[0]), "+f"((d)[1]), "+f"((d)[2]), "+f"((d)[3]) \
        : "r"((a)[0]), "r"((a)[1]), "r"((a)[2]), "r"((a)[3]), "r"(b0), "r"(b1))

#define CP_ASYNC16(dst, src) \
    asm volatile("cp.async.cg.shared.global [%0], [%1], 16;" \
                 :: "r"(dst), "l"(src) : "memory")
#define CP_COMMIT()  asm volatile("cp.async.commit_group;" ::: "memory")
#define CP_WAIT0()   asm volatile("cp.async.wait_group 0;" ::: "memory")

__device__ __forceinline__ float fast_tanh(float v) {
    float t; asm("ex2.approx.f32 %0, %1;" : "=f"(t) : "f"(v * 2.885390081777927f));
    float r; asm("rcp.approx.f32 %0, %1;" : "=f"(r) : "f"(t + 1.0f));
    return fmaf(-2.0f, r, 1.0f);   // tanh(v) = 1 - 2/(e^{2v}+1)
}

// ---------------------------------------------------------------------------
// Kernel 0: W [256,512] fp32 -> fp16 pairs
// ---------------------------------------------------------------------------
__global__ __launch_bounds__(256) void wsplit_kernel(const float* __restrict__ W)
{
    const int i = blockIdx.x * 256 + threadIdx.x;   // pair index
    const float2 v = ((const float2*)W)[i];
    __half2 hp = __floats2half2_rn(v.x, v.y);
    g_wh[i] = *(unsigned int*)&hp;
}

// ---------------------------------------------------------------------------
// Kernel 1: e[t] = sum_a q[a]*tanh( (W x)[t,a] ) via mma.sync fp16.
// CTA tile: M=64 tokens x N=256 (FULL A). 8 warps as 2(m) x 4(n).
// Double-buffered; W via cp.async, X via regs (fp32->fp16 convert).
// ---------------------------------------------------------------------------
#define RSTRIDE 144              // bytes per smem row (64 fp16 + pad)
#define BUFSZ   46080            // X(64*144=9216) + W(256*144=36864)
#define SM_W_OFF 9216
#define SM_Q    92160            // 256 floats
#define SM_TOTAL 93184

__global__ __launch_bounds__(256, 2) void e_mma_kernel(
    const float* __restrict__ x, const float* __restrict__ q)
{
    extern __shared__ __align__(128) char smem[];
    const uint32_t sb = smem_u32(smem);
    const int tid  = threadIdx.x;
    const int lane = tid & 31;
    const int warp = tid >> 5;
    const int warp_m = warp & 1;
    const int warp_n = warp >> 1;
    const size_t m0 = (size_t)blockIdx.x * 64;

    float* sq = (float*)(smem + SM_Q);
    sq[tid] = q[tid];

    float acc[2][8][4];
#pragma unroll
    for (int mt = 0; mt < 2; mt++)
#pragma unroll
        for (int nt = 0; nt < 8; nt++)
#pragma unroll
            for (int j = 0; j < 4; j++) acc[mt][nt][j] = 0.f;

    const uint32_t a_off = (lane & 15) * RSTRIDE + ((lane >> 4) << 4);
    const uint32_t b_off = ((((lane >> 4) & 1) << 3) + (lane & 7)) * RSTRIDE
                         + (((lane >> 3) & 1) << 4);
    const uint32_t ax0 = sb + warp_m * 32 * RSTRIDE + a_off;
    const uint32_t bw0 = sb + SM_W_OFF + warp_n * 64 * RSTRIDE + b_off;

    const uint4* wh4 = (const uint4*)g_wh;   // [a][64 uint4 per row]

    // Prologue: fill buffer 0 for chunk 0
    {
        float4 xv[4];
#pragma unroll
        for (int i = 0; i < 4; i++) {
            const int idx = i * 256 + tid;
            xv[i] = *(const float4*)(x + (m0 + (idx >> 4)) * HH + (idx & 15) * 4);
        }
#pragma unroll
        for (int i = 0; i < 8; i++) {
            const int g  = i * 256 + tid;
            const int row = g >> 3;
            const int cc  = g & 7;
            CP_ASYNC16(sb + SM_W_OFF + row * RSTRIDE + cc * 16,
                       wh4 + (size_t)row * 64 + cc);
        }
        CP_COMMIT();
#pragma unroll
        for (int i = 0; i < 4; i++) {
            const int idx = i * 256 + tid;
            const uint32_t bo = (idx >> 4) * RSTRIDE + (idx & 15) * 8;
            __half2 h01 = __floats2half2_rn(xv[i].x, xv[i].y);
            __half2 h23 = __floats2half2_rn(xv[i].z, xv[i].w);
            unsigned long long hp;
            asm("mov.b64 %0, {%1, %2};" : "=l"(hp)
                : "r"(*(unsigned int*)&h01), "r"(*(unsigned int*)&h23));
            *(unsigned long long*)(smem + bo) = hp;
        }
        CP_WAIT0();
        __syncthreads();
    }

    for (int c = 0; c < 8; c++) {
        const uint32_t cur = (c & 1) * BUFSZ;
        const uint32_t nxt = ((c + 1) & 1) * BUFSZ;

        float4 xv[4];
        if (c < 7) {
            const int kk = (c + 1) * 64;
#pragma unroll
            for (int i = 0; i < 4; i++) {
                const int idx = i * 256 + tid;
                xv[i] = *(const float4*)(x + (m0 + (idx >> 4)) * HH + kk + (idx & 15) * 4);
            }
#pragma unroll
            for (int i = 0; i < 8; i++) {
                const int g  = i * 256 + tid;
                const int row = g >> 3;
                const int cc  = g & 7;
                CP_ASYNC16(sb + nxt + SM_W_OFF + row * RSTRIDE + cc * 16,
                           wh4 + (size_t)row * 64 + (kk >> 3) + cc);
            }
            CP_COMMIT();
        }

        const uint32_t ax = ax0 + cur;
        const uint32_t bw = bw0 + cur;
#pragma unroll
        for (int ks = 0; ks < 4; ks++) {
            uint32_t Bv[16];
#pragma unroll
            for (int jp = 0; jp < 4; jp++)
                LDSM_X4(&Bv[jp * 4], bw + jp * 16 * RSTRIDE + ks * 32);
            uint32_t A0[4], A1[4];
            LDSM_X4(A0, ax + ks * 32);
            LDSM_X4(A1, ax + 16 * RSTRIDE + ks * 32);
#pragma unroll
            for (int nt = 0; nt < 8; nt++) {
                const int bi = (nt >> 1) * 4 + (nt & 1) * 2;
                HMMA16816(acc[0][nt], A0, Bv[bi], Bv[bi + 1]);
            }
#pragma unroll
            for (int nt = 0; nt < 8; nt++) {
                const int bi = (nt >> 1) * 4 + (nt & 1) * 2;
                HMMA16816(acc[1][nt], A1, Bv[bi], Bv[bi + 1]);
            }
        }

        if (c < 7) {
#pragma unroll
            for (int i = 0; i < 4; i++) {
                const int idx = i * 256 + tid;
                const uint32_t bo = (idx >> 4) * RSTRIDE + (idx & 15) * 8;
                __half2 h01 = __floats2half2_rn(xv[i].x, xv[i].y);
                __half2 h23 = __floats2half2_rn(xv[i].z, xv[i].w);
                unsigned long long hp;
                asm("mov.b64 %0, {%1, %2};" : "=l"(hp)
                    : "r"(*(unsigned int*)&h01), "r"(*(unsigned int*)&h23));
                *(unsigned long long*)(smem + nxt + bo) = hp;
            }
            CP_WAIT0();
            __syncthreads();
        }
    }

    // Epilogue: s = sum_cols q[col]*tanh(D) per owned row
    float s[2][2] = {{0.f, 0.f}, {0.f, 0.f}};
#pragma unroll
    for (int mt = 0; mt < 2; mt++)
#pragma unroll
        for (int nt = 0; nt < 8; nt++) {
            const int col = warp_n * 64 + nt * 8 + 2 * (lane & 3);
            const float q0 = sq[col], q1 = sq[col + 1];
            s[mt][0] = fmaf(q0, fast_tanh(acc[mt][nt][0]),
                       fmaf(q1, fast_tanh(acc[mt][nt][1]), s[mt][0]));
            s[mt][1] = fmaf(q0, fast_tanh(acc[mt][nt][2]),
                       fmaf(q1, fast_tanh(acc[mt][nt][3]), s[mt][1]));
        }
#pragma unroll
    for (int mt = 0; mt < 2; mt++)
#pragma unroll
        for (int rh = 0; rh < 2; rh++) {
            float v = s[mt][rh];
            v += __shfl_xor_sync(0xffffffffu, v, 1);
            v += __shfl_xor_sync(0xffffffffu, v, 2);
            s[mt][rh] = v;
        }

    __syncthreads();               // all ldmatrix done; reuse smem
    float* red = (float*)smem;     // [4 warp_n][64 rows]
    if ((lane & 3) == 0) {
#pragma unroll
        for (int mt = 0; mt < 2; mt++)
#pragma unroll
            for (int rh = 0; rh < 2; rh++)
                red[warp_n * 64 + warp_m * 32 + mt * 16 + rh * 8 + (lane >> 2)]
                    = s[mt][rh];
    }
    __syncthreads();
    if (tid < 64)
        g_e[m0 + tid] = (red[tid] + red[64 + tid])
                      + (red[128 + tid] + red[192 + tid]);
}

// ---------------------------------------------------------------------------
// Kernel 2: per-batch  w_t = exp(e_t - max), inclusive prefix P_s, ip = 1/P_s
// ---------------------------------------------------------------------------
__global__ __launch_bounds__(256) void scan_kernel()
{
    __shared__ float se[SS];
    __shared__ float sr[256];
    const int b   = blockIdx.x;
    const int tid = threadIdx.x;
    const int base = b * SS;

    for (int i = tid; i < SS; i += 256) se[i] = g_e[base + i];
    __syncthreads();

    float m = -1e30f;
    for (int i = tid; i < SS; i += 256) m = fmaxf(m, se[i]);
    sr[tid] = m;
    __syncthreads();
    for (int o = 128; o; o >>= 1) {
        if (tid < o) sr[tid] = fmaxf(sr[tid], sr[tid + o]);
        __syncthreads();
    }
    const float M = sr[0];
    __syncthreads();

    const int j0 = tid * 8;
    float wloc[8];
    float run = 0.f;
#pragma unroll
    for (int j = 0; j < 8; j++) {
        wloc[j] = expf(se[j0 + j] - M);
        run += wloc[j];
    }
    sr[tid] = run;
    __syncthreads();
    for (int o = 1; o < 256; o <<= 1) {
        const float v = (tid >= o) ? sr[tid - o] : 0.f;
        __syncthreads();
        sr[tid] += v;
        __syncthreads();
    }
    float acc = sr[tid] - run;
#pragma unroll
    for (int j = 0; j < 8; j++) {
        acc += wloc[j];
        g_w [base + j0 + j] = wloc[j];
        g_ip[base + j0 + j] = 1.0f / acc;
    }
}

// ---------------------------------------------------------------------------
// Kernel 3a: chunk sums T[b,c,h] = sum_{t in chunk} w_t * x[b,t,h]
// ---------------------------------------------------------------------------
__global__ __launch_bounds__(128) void chunk_kernel(const float* __restrict__ x)
{
    __shared__ float sw[CS];
    const int c = blockIdx.x;
    const int b = blockIdx.y;
    const int tbase = b * SS + c * CS;
    if (threadIdx.x < CS) sw[threadIdx.x] = g_w[tbase + threadIdx.x];
    __syncthreads();

    const float4* xp = (const float4*)(x + (size_t)tbase * HH) + threadIdx.x;
    float4 s = make_float4(0.f, 0.f, 0.f, 0.f);
#pragma unroll
    for (int t = 0; t < CS; t++) {
        const float4 v = xp[t * (HH/4)];
        const float w = sw[t];
        s.x = fmaf(w, v.x, s.x);
        s.y = fmaf(w, v.y, s.y);
        s.z = fmaf(w, v.z, s.z);
        s.w = fmaf(w, v.w, s.w);
    }
    ((float4*)(g_chunk + (size_t)(b * NC + c) * HH))[threadIdx.x] = s;
}

// ---------------------------------------------------------------------------
// Kernel 3p: exclusive prefix over chunks
// ---------------------------------------------------------------------------
__global__ __launch_bounds__(128) void chunkpre_kernel()
{
    const int b = blockIdx.x;
    const int h = blockIdx.y * 128 + threadIdx.x;
    float acc = 0.f;
#pragma unroll 4
    for (int c = 0; c < NC; c++) {
        const size_t idx = (size_t)(b * NC + c) * HH + h;
        const float v = g_chunk[idx];
        g_chunkpre[idx] = acc;
        acc += v;
    }
}

// ---------------------------------------------------------------------------
// Kernel 3b: a[b,s,h] = (chunkpre + running sum) * ip[b,s]
// ---------------------------------------------------------------------------
__global__ __launch_bounds__(128) void a_kernel(
    const float* __restrict__ x, float* __restrict__ a_out)
{
    __shared__ float sw[CS];
    __shared__ float sip[CS];
    const int c = blockIdx.x;
    const int b = blockIdx.y;
    const int tbase = b * SS + c * CS;
    if (threadIdx.x < CS) {
        sw [threadIdx.x] = g_w [tbase + threadIdx.x];
        sip[threadIdx.x] = g_ip[tbase + threadIdx.x];
    }
    __syncthreads();

    float4 acc = ((const float4*)(g_chunkpre + (size_t)(b * NC + c) * HH))[threadIdx.x];

    const float4* xp = (const float4*)(x + (size_t)tbase * HH) + threadIdx.x;
    float4* op = (float4*)(a_out + (size_t)tbase * HH) + threadIdx.x;
#pragma unroll
    for (int t = 0; t < CS; t++) {
        const float4 v = xp[t * (HH/4)];
        const float w = sw[t];
        acc.x = fmaf(w, v.x, acc.x);
        acc.y = fmaf(w, v.y, acc.y);
        acc.z = fmaf(w, v.z, acc.z);
        acc.w = fmaf(w, v.w, acc.w);
        const float ip = sip[t];
        __stcs(op + t * (HH/4),
               make_float4(acc.x * ip, acc.y * ip, acc.z * ip, acc.w * ip));
    }
}

// ---------------------------------------------------------------------------
// Kernel 4: d[b,s,t] = (t<=s) ? w[b,t]*ip[b,s] : 0  — 32 rows per CTA,
// 512 threads: one float4 store per thread per row.
// ---------------------------------------------------------------------------
#define DROWS 32
__global__ __launch_bounds__(512) void d_kernel(float* __restrict__ dd)
{
    __shared__ float4 sw4[SS/4];   // 8 KB
    __shared__ float sip[DROWS];
    const int blk = blockIdx.x;            // 1024 blocks
    const int b  = blk >> 6;               // 64 blocks per batch
    const int s0 = (blk & 63) * DROWS;

    const float4* w4 = (const float4*)(g_w + ((size_t)b << 11));
    if (threadIdx.x < SS/4) sw4[threadIdx.x] = w4[threadIdx.x];
    if (threadIdx.x < DROWS) sip[threadIdx.x] = g_ip[(b << 11) + s0 + threadIdx.x];
    __syncthreads();

    const int i  = threadIdx.x;            // float4 index within row
    const int t0 = i * 4;
    const float4 wv = sw4[i];
#pragma unroll 4
    for (int r = 0; r < DROWS; r++) {
        const int s = s0 + r;
        const float ip = sip[r];
        float4 out;
        if (t0 + 3 <= s) {
            out.x = wv.x * ip; out.y = wv.y * ip;
            out.z = wv.z * ip; out.w = wv.w * ip;
        } else if (t0 > s) {
            out.x = out.y = out.z = out.w = 0.f;
        } else {
            out.x = (t0     <= s) ? wv.x * ip : 0.f;
            out.y = (t0 + 1 <= s) ? wv.y * ip : 0.f;
            out.z = (t0 + 2 <= s) ? wv.z * ip : 0.f;
            out.w = (t0 + 3 <= s) ? wv.w * ip : 0.f;
        }
        __stcs((float4*)(dd + ((size_t)(b << 11) + s) * SS) + i, out);
    }
}

// ---------------------------------------------------------------------------
extern "C" void kernel_launch(void* const* d_in, const int* in_sizes, int n_in,
                              void* d_out, int out_size)
{
    const float* x = (const float*)d_in[0];   // [B,S,H]
    const float* W = (const float*)d_in[1];   // [A,H]
    const float* q = (const float*)d_in[2];   // [1,A]
    float* a_out = (float*)d_out;             // [B,S,1,H]
    float* dd    = (float*)d_out + A_ELEMS;   // [B,S,1,S]

    cudaFuncSetAttribute(e_mma_kernel,
                         cudaFuncAttributeMaxDynamicSharedMemorySize, SM_TOTAL);

    wsplit_kernel  <<<AA * HH / 512, 256>>>(W);
    e_mma_kernel   <<<BS / 64, 256, SM_TOTAL>>>(x, q);
    scan_kernel    <<<BB, 256>>>();
    chunk_kernel   <<<dim3(NC, BB), 128>>>(x);
    chunkpre_kernel<<<dim3(BB, HH / 128), 128>>>();
    a_kernel       <<<dim3(NC, BB), 128>>>(x, a_out);
    d_kernel       <<<BS / DROWS, 512>>>(dd);
}